// round 12
// baseline (speedup 1.0000x reference)
#include <cuda_runtime.h>

#define BB 4
#define HH 64
#define WW 64
#define LL 4096
#define DM 96
#define DI 192
#define DS 16
#define DR 6
#define NPROJ 38
#define CHN 16             // number of scan chunks
#define CH2 256            // chunk length = LL/CHN
#define DXPAD4 16          // float4 pad around g_dx4 (prefetch overrun)
#define BCPAD 64
#define B2PAD 64

// ---------------- scratch ----------------
__device__ __align__(16) float  g_xcraw[BB * LL * DI];
__device__ __align__(16) float  g_siluz[BB * LL * DI];
__device__ __align__(16) float  g_xca  [BB * LL * DI];
// dx packed: [(b,m)][dg=d/4][pos/2][dl=d%4] float4 = (del(p),x(p),del(p+1),x(p+1))
__device__ __align__(16) float4 g_dx4_raw[DXPAD4 + BB * 2 * (DI / 4) * (LL / 2) * 4 + DXPAD4];
__device__ __align__(16) float4 g_bc_raw[BCPAD + BB * 2 * LL * 8 + BCPAD];
__device__ __align__(16) float2 g_b2_raw[B2PAD + BB * 2 * LL * 8 + B2PAD];
__device__ __align__(16) float  g_y0   [BB * LL * DI];            // m=0 pair (fwd+bwd summed)
__device__ __align__(16) float  g_y1   [BB * LL * DI];            // m=1 pair, stored transposed
__device__ __align__(16) float  g_h    [BB * 4 * CHN * DI * 16];
__device__ __align__(16) float  g_sd   [BB * 4 * CHN * DI];

__device__ __forceinline__ float silu_f(float v) {
    return v * __frcp_rn(1.f + __expf(-v));
}
__device__ __forceinline__ float ex2f(float x) {
    float y; asm("ex2.approx.ftz.f32 %0, %1;" : "=f"(y) : "f"(x)); return y;
}

// ---------------- kernel 1: xz = x @ W_in ----------------
__global__ void k_in_gemm(const float* __restrict__ x, const float* __restrict__ Win) {
    __shared__ __align__(16) float xs[64][96];
    __shared__ __align__(16) float ws[96][64];
    const int t = threadIdx.x;                   // 256
    const int row0 = blockIdx.x * 64;
    const int col0 = blockIdx.y * 64;

    {
        const float4* xg = (const float4*)(x + (size_t)row0 * DM);
        float4* xv = (float4*)&xs[0][0];
        #pragma unroll
        for (int i = 0; i < 6; i++) xv[t + i * 256] = xg[t + i * 256];
    }
    {
        #pragma unroll
        for (int i = 0; i < 6; i++) {
            const int idx = t + i * 256;
            const int k = idx >> 4, c4 = idx & 15;
            *(float4*)&ws[k][c4 * 4] = *(const float4*)&Win[k * (2 * DI) + col0 + c4 * 4];
        }
    }
    __syncthreads();

    const int tx = t & 15, ty = t >> 4;
    float acc[4][4];
    #pragma unroll
    for (int i = 0; i < 4; i++)
        #pragma unroll
        for (int jj = 0; jj < 4; jj++) acc[i][jj] = 0.f;

    #pragma unroll 8
    for (int kk = 0; kk < 96; kk++) {
        const float4 bv = *(const float4*)&ws[kk][tx * 4];
        const float a0 = xs[ty * 4 + 0][kk];
        const float a1 = xs[ty * 4 + 1][kk];
        const float a2 = xs[ty * 4 + 2][kk];
        const float a3 = xs[ty * 4 + 3][kk];
        acc[0][0] += a0 * bv.x; acc[0][1] += a0 * bv.y; acc[0][2] += a0 * bv.z; acc[0][3] += a0 * bv.w;
        acc[1][0] += a1 * bv.x; acc[1][1] += a1 * bv.y; acc[1][2] += a1 * bv.z; acc[1][3] += a1 * bv.w;
        acc[2][0] += a2 * bv.x; acc[2][1] += a2 * bv.y; acc[2][2] += a2 * bv.z; acc[2][3] += a2 * bv.w;
        acc[3][0] += a3 * bv.x; acc[3][1] += a3 * bv.y; acc[3][2] += a3 * bv.z; acc[3][3] += a3 * bv.w;
    }

    if (col0 < DI) {
        #pragma unroll
        for (int i = 0; i < 4; i++) {
            const int row = row0 + ty * 4 + i;
            *(float4*)&g_xcraw[(size_t)row * DI + col0 + tx * 4] =
                make_float4(acc[i][0], acc[i][1], acc[i][2], acc[i][3]);
        }
    } else {
        const int c = col0 - DI;
        #pragma unroll
        for (int i = 0; i < 4; i++) {
            const int row = row0 + ty * 4 + i;
            *(float4*)&g_siluz[(size_t)row * DI + c + tx * 4] =
                make_float4(silu_f(acc[i][0]), silu_f(acc[i][1]),
                            silu_f(acc[i][2]), silu_f(acc[i][3]));
        }
    }
}

// ---------------- kernel 2: depthwise 3x3 conv + bias + SiLU ----------------
__global__ void k_conv(const float* __restrict__ cw, const float* __restrict__ cb) {
    const int idx = blockIdx.x * blockDim.x + threadIdx.x;
    if (idx >= BB * LL * (DI / 4)) return;
    const int cv = idx % (DI / 4);
    const int c  = cv * 4;
    const int l  = (idx / (DI / 4)) % LL;
    const int b  = idx / (LL * (DI / 4));
    const int h = l >> 6, w = l & 63;

    float4 acc = make_float4(0.f, 0.f, 0.f, 0.f);
    #pragma unroll
    for (int kh = 0; kh < 3; kh++) {
        const int hh = h + kh - 1;
        if (hh < 0 || hh >= HH) continue;
        #pragma unroll
        for (int kw = 0; kw < 3; kw++) {
            const int wv = w + kw - 1;
            if (wv < 0 || wv >= WW) continue;
            const float4 v  = *(const float4*)&g_xcraw[((size_t)(b * LL) + (hh * WW + wv)) * DI + c];
            const float4 wt = *(const float4*)&cw[(kh * 3 + kw) * DI + c];
            acc.x += v.x * wt.x; acc.y += v.y * wt.y;
            acc.z += v.z * wt.z; acc.w += v.w * wt.w;
        }
    }
    const float4 bv = *(const float4*)&cb[c];
    float4 o;
    o.x = silu_f(acc.x + bv.x);
    o.y = silu_f(acc.y + bv.y);
    o.z = silu_f(acc.z + bv.z);
    o.w = silu_f(acc.w + bv.w);
    *(float4*)&g_xca[((size_t)(b * LL) + l) * DI + c] = o;
}

// ---------------- kernel 3: x-proj + delta ----------------
__global__ __launch_bounds__(160) void k_proj(const float* __restrict__ Wx,
                                              const float* __restrict__ Wdt,
                                              const float* __restrict__ bdt) {
    __shared__ __align__(16) float xs[64][33];
    __shared__ __align__(16) float ws[32][40];
    __shared__ float xdbl[64][41];
    __shared__ float dsm[64][33];
    __shared__ float wdt_s[DR][DI];
    __shared__ float bdt_s[DI];
    const int t  = threadIdx.x;                   // 160
    const int p0 = blockIdx.x * 64;
    const int m  = blockIdx.y;
    const int b  = blockIdx.z;
    const int bm = b * 2 + m;
    const int tx = t % 10, ty = t / 10;

    for (int i = t; i < DR * DI; i += 160) ((float*)wdt_s)[i] = Wdt[i];
    for (int i = t; i < DI; i += 160) bdt_s[i] = bdt[i];
    __syncthreads();

    float acc[4][4];
    #pragma unroll
    for (int i = 0; i < 4; i++)
        #pragma unroll
        for (int q = 0; q < 4; q++) acc[i][q] = 0.f;

    for (int kt = 0; kt < 6; kt++) {
        __syncthreads();
        for (int i = t; i < 64 * 32; i += 160) {
            const int r = i >> 5, c = i & 31;
            const int p = p0 + r;
            const int src = m ? (((p & 63) << 6) | (p >> 6)) : p;
            xs[r][c] = g_xca[((size_t)b * LL + src) * DI + kt * 32 + c];
        }
        for (int i = t; i < 32 * 40; i += 160) {
            const int k = i / 40, j = i % 40;
            ws[k][j] = (j < NPROJ) ? Wx[(kt * 32 + k) * NPROJ + j] : 0.f;
        }
        __syncthreads();

        #pragma unroll 8
        for (int kk = 0; kk < 32; kk++) {
            const float4 bv = *(const float4*)&ws[kk][tx * 4];
            const float a0 = xs[ty * 4 + 0][kk];
            const float a1 = xs[ty * 4 + 1][kk];
            const float a2 = xs[ty * 4 + 2][kk];
            const float a3 = xs[ty * 4 + 3][kk];
            acc[0][0] += a0 * bv.x; acc[0][1] += a0 * bv.y; acc[0][2] += a0 * bv.z; acc[0][3] += a0 * bv.w;
            acc[1][0] += a1 * bv.x; acc[1][1] += a1 * bv.y; acc[1][2] += a1 * bv.z; acc[1][3] += a1 * bv.w;
            acc[2][0] += a2 * bv.x; acc[2][1] += a2 * bv.y; acc[2][2] += a2 * bv.z; acc[2][3] += a2 * bv.w;
            acc[3][0] += a3 * bv.x; acc[3][1] += a3 * bv.y; acc[3][2] += a3 * bv.z; acc[3][3] += a3 * bv.w;
        }
    }
    #pragma unroll
    for (int i = 0; i < 4; i++)
        #pragma unroll
        for (int q = 0; q < 4; q++)
            xdbl[ty * 4 + i][tx * 4 + q] = acc[i][q];
    __syncthreads();

    {
        float2* bc2 = (float2*)(g_bc_raw + BCPAD);
        for (int i = t; i < 64 * 16; i += 160) {
            const int pi = i >> 4, n = i & 15;
            bc2[(((size_t)bm * LL + p0 + pi) * 8 + (n & 7)) * 2 + (n >> 3)] =
                make_float2(xdbl[pi][DR + n], xdbl[pi][DR + DS + n]);
        }
        float2* b2 = g_b2_raw + B2PAD;
        for (int i = t; i < 64 * 8; i += 160) {
            const int pi = i >> 3, jj = i & 7;
            b2[((size_t)bm * LL + p0 + pi) * 8 + jj] =
                make_float2(xdbl[pi][DR + jj], xdbl[pi][DR + 8 + jj]);
        }
    }

    float4* dx4 = g_dx4_raw + DXPAD4;
    for (int dt = 0; dt < 6; dt++) {
        __syncthreads();
        for (int i = t; i < 64 * 32; i += 160) {
            const int r = i >> 5, c = i & 31;
            const int p = p0 + r;
            const int src = m ? (((p & 63) << 6) | (p >> 6)) : p;
            xs[r][c] = g_xca[((size_t)b * LL + src) * DI + dt * 32 + c];
        }
        __syncthreads();
        for (int i = t; i < 32 * 64; i += 160) {
            const int dl32 = i >> 6, pi = i & 63;
            const int d = dt * 32 + dl32;
            float v = bdt_s[d];
            #pragma unroll
            for (int r = 0; r < DR; r++) v += xdbl[pi][r] * wdt_s[r][d];
            dsm[pi][dl32] = (v > 20.f) ? v : log1pf(__expf(v));
        }
        __syncthreads();
        // pack (del,x) pairs into group-interleaved float4 layout
        for (int i = t; i < 32 * 32; i += 160) {
            const int dlx = i & 31, pp = i >> 5;
            const int d = dt * 32 + dlx;
            const int dg = d >> 2, dl = d & 3;
            const size_t idx = (((size_t)(bm * (DI / 4) + dg)) * (LL / 2) + (p0 >> 1) + pp) * 4 + dl;
            dx4[idx] = make_float4(dsm[2 * pp][dlx], xs[2 * pp][dlx],
                                   dsm[2 * pp + 1][dlx], xs[2 * pp + 1][dlx]);
        }
    }
}

// ---------------- scan macros ----------------
// dx loads: per thread float4 = (del,x,del,x) for 2 positions of its own d.
// scan1 (B-only) loads
#define LOADB1(S, pd_, pq_)                                            \
    S##_dxa = (pd_)[0]; S##_dxb = (pd_)[4];                            \
    S##_b0 = (pq_)[0];  S##_b1 = (pq_)[8];                             \
    S##_b2 = (pq_)[16]; S##_b3 = (pq_)[24];

// scan2 (full bc) loads
#define LOADG(S, pd_, pb_)                                             \
    S##_dxa = (pd_)[0]; S##_dxb = (pd_)[4];                            \
    S##_c0 = (pb_)[0];  S##_c1 = (pb_)[8];                             \
    S##_c2 = (pb_)[16]; S##_c3 = (pb_)[24];

#define STEPQ(del, xv, bv2) {                                          \
    const float dA0 = ex2f((del) * A0);                                \
    const float dA1 = ex2f((del) * A1);                                \
    const float tv = (del) * (xv);                                     \
    h0 = fmaf(dA0, h0, tv * (bv2).x);                                  \
    h1 = fmaf(dA1, h1, tv * (bv2).y);                                  \
    sd += (del); }

#define GBQ_F(S) {                                                     \
    STEPQ(S##_dxa.x, S##_dxa.y, S##_b0);                               \
    STEPQ(S##_dxa.z, S##_dxa.w, S##_b1);                               \
    STEPQ(S##_dxb.x, S##_dxb.y, S##_b2);                               \
    STEPQ(S##_dxb.z, S##_dxb.w, S##_b3); }

#define GBQ_R(S) {                                                     \
    STEPQ(S##_dxb.z, S##_dxb.w, S##_b3);                               \
    STEPQ(S##_dxb.x, S##_dxb.y, S##_b2);                               \
    STEPQ(S##_dxa.z, S##_dxa.w, S##_b1);                               \
    STEPQ(S##_dxa.x, S##_dxa.y, S##_b0); }

#define WALK1_F(lo, hi) {                                              \
    float4 s0_dxa, s0_dxb; float2 s0_b0, s0_b1, s0_b2, s0_b3;          \
    float4 s1_dxa, s1_dxb; float2 s1_b0, s1_b1, s1_b2, s1_b3;          \
    const float4* pd = dxr + (size_t)((lo) >> 1) * 4;                  \
    const float2* pq = bqr + (size_t)(lo) * 8;                         \
    LOADB1(s0, pd, pq);                                                \
    LOADB1(s1, pd + 8, pq + 32);                                       \
    const float4* pdn = pd + 16;                                       \
    const float2* pqn = pq + 64;                                       \
    for (int it = ((hi) - (lo)) >> 3; it > 0; it--) {                  \
        GBQ_F(s0);                                                     \
        LOADB1(s0, pdn, pqn);                                          \
        GBQ_F(s1);                                                     \
        LOADB1(s1, pdn + 8, pqn + 32);                                 \
        pdn += 16; pqn += 64;                                          \
    } }

#define WALK1_R(lo, hi) {                                              \
    float4 s0_dxa, s0_dxb; float2 s0_b0, s0_b1, s0_b2, s0_b3;          \
    float4 s1_dxa, s1_dxb; float2 s1_b0, s1_b1, s1_b2, s1_b3;          \
    const float4* pd = dxr + (size_t)((hi) >> 1) * 4 - 8;              \
    const float2* pq = bqr + (size_t)((hi) - 4) * 8;                   \
    LOADB1(s0, pd, pq);                                                \
    LOADB1(s1, pd - 8, pq - 32);                                       \
    const float4* pdn = pd - 16;                                       \
    const float2* pqn = pq - 64;                                       \
    for (int it = ((hi) - (lo)) >> 3; it > 0; it--) {                  \
        GBQ_R(s0);                                                     \
        LOADB1(s0, pdn, pqn);                                          \
        GBQ_R(s1);                                                     \
        LOADB1(s1, pdn - 8, pqn - 32);                                 \
        pdn -= 16; pqn -= 64;                                          \
    } }

#define STEPS(del, xv, bcv, yi) {                                      \
    const float dA0 = ex2f((del) * A0);                                \
    const float dA1 = ex2f((del) * A1);                                \
    const float tv = (del) * (xv);                                     \
    h0 = fmaf(dA0, h0, tv * (bcv).x);                                  \
    h1 = fmaf(dA1, h1, tv * (bcv).z);                                  \
    float y = fmaf(h1, (bcv).w, h0 * (bcv).y);                         \
    y += __shfl_xor_sync(0xffffffffu, y, 1);                           \
    y += __shfl_xor_sync(0xffffffffu, y, 2);                           \
    y += __shfl_xor_sync(0xffffffffu, y, 4);                           \
    if (j == 0) yt[(yi) * 16] = y; }

#define GBS_F(S, sp) {                                                 \
    STEPS(S##_dxa.x, S##_dxa.y, S##_c0, sp);                           \
    STEPS(S##_dxa.z, S##_dxa.w, S##_c1, (sp) + 1);                     \
    STEPS(S##_dxb.x, S##_dxb.y, S##_c2, (sp) + 2);                     \
    STEPS(S##_dxb.z, S##_dxb.w, S##_c3, (sp) + 3); }

#define GBS_R(S, sp) {                                                 \
    STEPS(S##_dxb.z, S##_dxb.w, S##_c3, (sp) + 3);                     \
    STEPS(S##_dxb.x, S##_dxb.y, S##_c2, (sp) + 2);                     \
    STEPS(S##_dxa.z, S##_dxa.w, S##_c1, (sp) + 1);                     \
    STEPS(S##_dxa.x, S##_dxa.y, S##_c0, sp); }

#define WALK2_F(lo, hi, GB) {                                          \
    float4 s0_dxa, s0_dxb, s0_c0, s0_c1, s0_c2, s0_c3;                 \
    float4 s1_dxa, s1_dxb, s1_c0, s1_c1, s1_c2, s1_c3;                 \
    const float4* pd = dxr + (size_t)((lo) >> 1) * 4;                  \
    const float4* pb = bcr + (size_t)(lo) * 8;                         \
    LOADG(s0, pd, pb);                                                 \
    LOADG(s1, pd + 8, pb + 32);                                        \
    const float4* pdn = pd + 16;                                       \
    const float4* pbn = pb + 64;                                       \
    int sp = (lo);                                                     \
    for (int it = ((hi) - (lo)) >> 3; it > 0; it--) {                  \
        GB(s0, sp);                                                    \
        LOADG(s0, pdn, pbn);                                           \
        GB(s1, (sp + 4));                                              \
        LOADG(s1, pdn + 8, pbn + 32);                                  \
        pdn += 16; pbn += 64; sp += 8;                                 \
    } }

#define WALK2_R(lo, hi, GB) {                                          \
    float4 s0_dxa, s0_dxb, s0_c0, s0_c1, s0_c2, s0_c3;                 \
    float4 s1_dxa, s1_dxb, s1_c0, s1_c1, s1_c2, s1_c3;                 \
    const float4* pd = dxr + (size_t)((hi) >> 1) * 4 - 8;              \
    const float4* pb = bcr + (size_t)((hi) - 4) * 8;                   \
    LOADG(s0, pd, pb);                                                 \
    LOADG(s1, pd - 8, pb - 32);                                        \
    const float4* pdn = pd - 16;                                       \
    const float4* pbn = pb - 64;                                       \
    int sp = (hi) - 4;                                                 \
    for (int it = ((hi) - (lo)) >> 3; it > 0; it--) {                  \
        GB(s0, sp);                                                    \
        LOADG(s0, pdn, pbn);                                           \
        GB(s1, (sp - 4));                                              \
        LOADG(s1, pdn - 8, pbn - 32);                                  \
        pdn -= 16; pbn -= 64; sp -= 8;                                 \
    } }

// ---------------- kernel 4a: phase-1 chunk summaries ----------------
__global__ __launch_bounds__(128) void k_scan1(const float* __restrict__ A_logs) {
    const int k  = blockIdx.y >> 4;
    const int ch = blockIdx.y & 15;
    if (ch == CHN - 1) return;                 // last chunk summary feeds nothing
    const int b  = blockIdx.z;
    const int lane = threadIdx.x & 31;
    const int w  = threadIdx.x >> 5;
    const int d  = blockIdx.x * 16 + w * 4 + (lane >> 3);
    const int j  = lane & 7;
    const int m = k >> 1, rev = k & 1;
    const int bm = b * 2 + m;
    const float L2E = 1.4426950408889634f;

    const float A0 = -__expf(__ldg(&A_logs[(k * DI + d) * DS + j]))     * L2E;
    const float A1 = -__expf(__ldg(&A_logs[(k * DI + d) * DS + j + 8])) * L2E;

    const float4* dxr = g_dx4_raw + DXPAD4 +
        ((size_t)(bm * (DI / 4) + blockIdx.x * 4 + w)) * (LL / 2) * 4 + (lane >> 3);
    const float2* bqr = g_b2_raw + B2PAD + (size_t)bm * LL * 8 + j;

    float h0 = 0.f, h1 = 0.f, sd = 0.f;

    if (!rev) { WALK1_F(ch * CH2, (ch + 1) * CH2); }
    else      { WALK1_R(LL - (ch + 1) * CH2, LL - ch * CH2); }

    const int base = (((b * 4 + k) * CHN + ch) * DI + d) * 16;
    g_h[base + j]     = h0;
    g_h[base + j + 8] = h1;
    if (j == 0) g_sd[((b * 4 + k) * CHN + ch) * DI + d] = sd;
}

// ---------------- kernel 4b: chunk-prefix combine ----------------
__global__ void k_comb(const float* __restrict__ A_logs) {
    const int idx = blockIdx.x * blockDim.x + threadIdx.x;
    if (idx >= BB * 4 * DI * 16) return;
    const int n = idx & 15;
    const int d = (idx >> 4) % DI;
    const int k = ((idx >> 4) / DI) & 3;
    const int b2 = idx / (4 * DI * 16);
    const float L2E = 1.4426950408889634f;
    const float A = -__expf(A_logs[(k * DI + d) * DS + n]) * L2E;

    float hin = 0.f;
    #pragma unroll
    for (int c = 0; c < CHN; c++) {
        const int base = (((b2 * 4 + k) * CHN + c) * DI + d) * 16;
        const float hc = g_h[base + n];
        const float P  = ex2f(A * g_sd[((b2 * 4 + k) * CHN + c) * DI + d]);
        g_h[base + n] = hin;
        hin = fmaf(P, hin, hc);                // garbage hc at c==CHN-1 is discarded
    }
}

// ---------------- kernel 4c: phase-3 emit, direction-merged, atomic-free ------
__global__ __launch_bounds__(256) void k_scan2(const float* __restrict__ A_logs) {
    __shared__ float ya[2][CH2][16];           // 32 KB
    const int m  = blockIdx.y >> 4;            // direction pair
    const int ch = blockIdx.y & 15;            // position chunk
    const int b  = blockIdx.z;
    const int w  = threadIdx.x >> 5;           // 0..7
    const int fwd = (w < 4) ? 1 : 0;
    const int k  = m * 2 + (fwd ? 0 : 1);
    const int lane = threadIdx.x & 31;
    const int wd = w & 3;
    const int dl = wd * 4 + (lane >> 3);       // d-local 0..15
    const int d  = blockIdx.x * 16 + dl;
    const int j  = lane & 7;
    const int bm = b * 2 + m;
    const float L2E = 1.4426950408889634f;

    const float A0 = -__expf(__ldg(&A_logs[(k * DI + d) * DS + j]))     * L2E;
    const float A1 = -__expf(__ldg(&A_logs[(k * DI + d) * DS + j + 8])) * L2E;

    const int p0g = ch * CH2;
    const float4* dxr = g_dx4_raw + DXPAD4 +
        (((size_t)(bm * (DI / 4) + blockIdx.x * 4 + wd)) * (LL / 2) + (p0g >> 1)) * 4 + (lane >> 3);
    const float4* bcr = g_bc_raw + BCPAD + ((size_t)bm * LL + p0g) * 8 + j;
    float* yt = &ya[fwd ? 0 : 1][0][dl];

    const int chs = fwd ? ch : (CHN - 1 - ch);
    const int base = (((b * 4 + k) * CHN + chs) * DI + d) * 16;
    float h0 = g_h[base + j];
    float h1 = g_h[base + j + 8];

    if (fwd) { WALK2_F(0, CH2, GBS_F); }
    else     { WALK2_R(0, CH2, GBS_R); }

    __syncthreads();

    float* yout = (m ? g_y1 : g_y0) + (size_t)b * LL * DI;
    for (int it = threadIdx.x; it < CH2 * 4; it += 256) {
        const int pl = it >> 2, q = it & 3;
        const float4 a = *(const float4*)&ya[0][pl][q * 4];
        const float4 bv = *(const float4*)&ya[1][pl][q * 4];
        const int p = p0g + pl;
        const int tgt = m ? (((p & 63) << 6) | (p >> 6)) : p;
        *(float4*)&yout[(size_t)tgt * DI + blockIdx.x * 16 + q * 4] =
            make_float4(a.x + bv.x, a.y + bv.y, a.z + bv.z, a.w + bv.w);
    }
}

// ---------------- kernel 5: out = ((y0+y1+xca*sumD) * siluz) @ W_out ----------
__global__ void k_out(const float* __restrict__ Wout, const float* __restrict__ Dsg,
                      float* __restrict__ out) {
    __shared__ __align__(16) float ins[64][96];
    __shared__ __align__(16) float ws[96][32];
    __shared__ float dsum_s[DI];
    const int t = threadIdx.x;                    // 128
    const int row0 = blockIdx.x * 64;
    const int col0 = blockIdx.y * 32;
    const int tx = t & 7, ty = t >> 3;

    for (int i = t; i < DI; i += 128)
        dsum_s[i] = Dsg[i] + Dsg[DI + i] + Dsg[2 * DI + i] + Dsg[3 * DI + i];

    float acc[4][4];
    #pragma unroll
    for (int i = 0; i < 4; i++)
        #pragma unroll
        for (int jj = 0; jj < 4; jj++) acc[i][jj] = 0.f;

    for (int kc = 0; kc < 2; kc++) {
        __syncthreads();
        #pragma unroll
        for (int i = 0; i < 12; i++) {
            const int idx = t + i * 128;
            const int r = idx / 24, k4 = idx % 24;
            const int c0 = kc * 96 + k4 * 4;
            const size_t gi = (size_t)(row0 + r) * DI + c0;
            const float4 y0 = *(const float4*)&g_y0[gi];
            const float4 y1 = *(const float4*)&g_y1[gi];
            const float4 xc = *(const float4*)&g_xca[gi];
            const float4 z  = *(const float4*)&g_siluz[gi];
            const float4 dv = *(const float4*)&dsum_s[c0];
            *(float4*)&ins[r][k4 * 4] = make_float4(
                (y0.x + y1.x + xc.x * dv.x) * z.x,
                (y0.y + y1.y + xc.y * dv.y) * z.y,
                (y0.z + y1.z + xc.z * dv.z) * z.z,
                (y0.w + y1.w + xc.w * dv.w) * z.w);
        }
        #pragma unroll
        for (int i = 0; i < 6; i++) {
            const int idx = t + i * 128;
            const int kk = idx / 8, c4 = idx % 8;
            *(float4*)&ws[kk][c4 * 4] = *(const float4*)&Wout[(kc * 96 + kk) * DM + col0 + c4 * 4];
        }
        __syncthreads();

        #pragma unroll 8
        for (int kk = 0; kk < 96; kk++) {
            const float4 bv = *(const float4*)&ws[kk][tx * 4];
            const float a0 = ins[ty * 4 + 0][kk];
            const float a1 = ins[ty * 4 + 1][kk];
            const float a2 = ins[ty * 4 + 2][kk];
            const float a3 = ins[ty * 4 + 3][kk];
            acc[0][0] += a0 * bv.x; acc[0][1] += a0 * bv.y; acc[0][2] += a0 * bv.z; acc[0][3] += a0 * bv.w;
            acc[1][0] += a1 * bv.x; acc[1][1] += a1 * bv.y; acc[1][2] += a1 * bv.z; acc[1][3] += a1 * bv.w;
            acc[2][0] += a2 * bv.x; acc[2][1] += a2 * bv.y; acc[2][2] += a2 * bv.z; acc[2][3] += a2 * bv.w;
            acc[3][0] += a3 * bv.x; acc[3][1] += a3 * bv.y; acc[3][2] += a3 * bv.z; acc[3][3] += a3 * bv.w;
        }
    }

    #pragma unroll
    for (int i = 0; i < 4; i++) {
        const int row = row0 + ty * 4 + i;
        *(float4*)&out[(size_t)row * DM + col0 + tx * 4] =
            make_float4(acc[i][0], acc[i][1], acc[i][2], acc[i][3]);
    }
}

// ---------------- launch ----------------
extern "C" void kernel_launch(void* const* d_in, const int* in_sizes, int n_in,
                              void* d_out, int out_size) {
    const float* x     = (const float*)d_in[0];
    const float* Win   = (const float*)d_in[1];
    const float* cw    = (const float*)d_in[2];
    const float* cb    = (const float*)d_in[3];
    const float* Wx    = (const float*)d_in[4];
    const float* Wdt   = (const float*)d_in[5];
    const float* bdt   = (const float*)d_in[6];
    const float* Alogs = (const float*)d_in[7];
    const float* Ds    = (const float*)d_in[8];
    const float* Wout  = (const float*)d_in[9];
    float* out = (float*)d_out;

    dim3 gg(BB * LL / 64, 6);
    k_in_gemm<<<gg, 256>>>(x, Win);
    k_conv<<<(BB * LL * (DI / 4) + 255) / 256, 256>>>(cw, cb);
    dim3 gp(LL / 64, 2, BB);
    k_proj<<<gp, 160>>>(Wx, Wdt, bdt);
    dim3 gs1(DI / 16, 4 * CHN, BB);
    k_scan1<<<gs1, 128>>>(Alogs);
    k_comb<<<(BB * 4 * DI * 16 + 255) / 256, 256>>>(Alogs);
    dim3 gs2(DI / 16, 2 * CHN, BB);      // y = pair*16 + chunk
    k_scan2<<<gs2, 256>>>(Alogs);
    dim3 go(BB * LL / 64, 3);
    k_out<<<go, 128>>>(Wout, Ds, out);
}

// round 13
// speedup vs baseline: 1.0213x; 1.0213x over previous
#include <cuda_runtime.h>

#define BB 4
#define HH 64
#define WW 64
#define LL 4096
#define DM 96
#define DI 192
#define DS 16
#define DR 6
#define NPROJ 38
#define CHN 16             // number of scan chunks
#define CH2 256            // chunk length = LL/CHN
#define DXPAD 16           // float2 pad around g_dx (prefetch overrun)
#define BCPAD 64           // float4 pad around g_bc (prefetch overrun)
#define B2PAD 64           // float4 pad around g_b2 (prefetch overrun)

// ---------------- scratch ----------------
__device__ __align__(16) float  g_xcraw[BB * LL * DI];
__device__ __align__(16) float  g_siluz[BB * LL * DI];
__device__ __align__(16) float  g_xca  [BB * LL * DI];
__device__ __align__(16) float2 g_dx_raw[DXPAD + BB * 2 * DI * LL + DXPAD];
__device__ __align__(16) float4 g_bc_raw[BCPAD + BB * 2 * LL * 8 + BCPAD];
// B pairs: [bm][pos/2][j] float4 = (Bj(p),Bj+8(p),Bj(p+1),Bj+8(p+1))
__device__ __align__(16) float4 g_b2_raw[B2PAD + BB * 2 * (LL / 2) * 8 + B2PAD];
__device__ __align__(16) float  g_ysum [BB * LL * DI];
__device__ __align__(16) float  g_h    [BB * 4 * CHN * DI * 16];  // chunk summaries
__device__ __align__(16) float  g_sd   [BB * 4 * CHN * DI];       // per-chunk delta sums

__device__ __forceinline__ float silu_f(float v) {
    return v * __frcp_rn(1.f + __expf(-v));
}
__device__ __forceinline__ float ex2f(float x) {
    float y; asm("ex2.approx.ftz.f32 %0, %1;" : "=f"(y) : "f"(x)); return y;
}

// ---------------- kernel 1: xz = x @ W_in ----------------
__global__ void k_in_gemm(const float* __restrict__ x, const float* __restrict__ Win) {
    __shared__ __align__(16) float xs[64][96];
    __shared__ __align__(16) float ws[96][64];
    const int t = threadIdx.x;                   // 256
    const int row0 = blockIdx.x * 64;
    const int col0 = blockIdx.y * 64;

    {
        const float4* xg = (const float4*)(x + (size_t)row0 * DM);
        float4* xv = (float4*)&xs[0][0];
        #pragma unroll
        for (int i = 0; i < 6; i++) xv[t + i * 256] = xg[t + i * 256];
    }
    {
        #pragma unroll
        for (int i = 0; i < 6; i++) {
            const int idx = t + i * 256;
            const int k = idx >> 4, c4 = idx & 15;
            *(float4*)&ws[k][c4 * 4] = *(const float4*)&Win[k * (2 * DI) + col0 + c4 * 4];
        }
    }
    __syncthreads();

    const int tx = t & 15, ty = t >> 4;
    float acc[4][4];
    #pragma unroll
    for (int i = 0; i < 4; i++)
        #pragma unroll
        for (int jj = 0; jj < 4; jj++) acc[i][jj] = 0.f;

    #pragma unroll 8
    for (int kk = 0; kk < 96; kk++) {
        const float4 bv = *(const float4*)&ws[kk][tx * 4];
        const float a0 = xs[ty * 4 + 0][kk];
        const float a1 = xs[ty * 4 + 1][kk];
        const float a2 = xs[ty * 4 + 2][kk];
        const float a3 = xs[ty * 4 + 3][kk];
        acc[0][0] += a0 * bv.x; acc[0][1] += a0 * bv.y; acc[0][2] += a0 * bv.z; acc[0][3] += a0 * bv.w;
        acc[1][0] += a1 * bv.x; acc[1][1] += a1 * bv.y; acc[1][2] += a1 * bv.z; acc[1][3] += a1 * bv.w;
        acc[2][0] += a2 * bv.x; acc[2][1] += a2 * bv.y; acc[2][2] += a2 * bv.z; acc[2][3] += a2 * bv.w;
        acc[3][0] += a3 * bv.x; acc[3][1] += a3 * bv.y; acc[3][2] += a3 * bv.z; acc[3][3] += a3 * bv.w;
    }

    if (col0 < DI) {
        #pragma unroll
        for (int i = 0; i < 4; i++) {
            const int row = row0 + ty * 4 + i;
            *(float4*)&g_xcraw[(size_t)row * DI + col0 + tx * 4] =
                make_float4(acc[i][0], acc[i][1], acc[i][2], acc[i][3]);
        }
    } else {
        const int c = col0 - DI;
        #pragma unroll
        for (int i = 0; i < 4; i++) {
            const int row = row0 + ty * 4 + i;
            *(float4*)&g_siluz[(size_t)row * DI + c + tx * 4] =
                make_float4(silu_f(acc[i][0]), silu_f(acc[i][1]),
                            silu_f(acc[i][2]), silu_f(acc[i][3]));
        }
    }
}

// ---------------- kernel 2: depthwise 3x3 conv + bias + SiLU ----------------
__global__ void k_conv(const float* __restrict__ cw, const float* __restrict__ cb) {
    const int idx = blockIdx.x * blockDim.x + threadIdx.x;
    if (idx >= BB * LL * (DI / 4)) return;
    const int cv = idx % (DI / 4);
    const int c  = cv * 4;
    const int l  = (idx / (DI / 4)) % LL;
    const int b  = idx / (LL * (DI / 4));
    const int h = l >> 6, w = l & 63;

    float4 acc = make_float4(0.f, 0.f, 0.f, 0.f);
    #pragma unroll
    for (int kh = 0; kh < 3; kh++) {
        const int hh = h + kh - 1;
        if (hh < 0 || hh >= HH) continue;
        #pragma unroll
        for (int kw = 0; kw < 3; kw++) {
            const int wv = w + kw - 1;
            if (wv < 0 || wv >= WW) continue;
            const float4 v  = *(const float4*)&g_xcraw[((size_t)(b * LL) + (hh * WW + wv)) * DI + c];
            const float4 wt = *(const float4*)&cw[(kh * 3 + kw) * DI + c];
            acc.x += v.x * wt.x; acc.y += v.y * wt.y;
            acc.z += v.z * wt.z; acc.w += v.w * wt.w;
        }
    }
    const float4 bv = *(const float4*)&cb[c];
    float4 o;
    o.x = silu_f(acc.x + bv.x);
    o.y = silu_f(acc.y + bv.y);
    o.z = silu_f(acc.z + bv.z);
    o.w = silu_f(acc.w + bv.w);
    *(float4*)&g_xca[((size_t)(b * LL) + l) * DI + c] = o;
}

// ---------------- kernel 3: x-proj + delta + ysum D-init ----------------
__global__ __launch_bounds__(160) void k_proj(const float* __restrict__ Wx,
                                              const float* __restrict__ Wdt,
                                              const float* __restrict__ bdt,
                                              const float* __restrict__ Dsg) {
    __shared__ __align__(16) float xs[64][33];
    __shared__ __align__(16) float ws[32][40];
    __shared__ float xdbl[64][41];
    __shared__ float wdt_s[DR][DI];
    __shared__ float bdt_s[DI];
    __shared__ float dsum_s[DI];
    const int t  = threadIdx.x;                   // 160
    const int p0 = blockIdx.x * 64;
    const int m  = blockIdx.y;
    const int b  = blockIdx.z;
    const int bm = b * 2 + m;
    const int tx = t % 10, ty = t / 10;

    for (int i = t; i < DR * DI; i += 160) ((float*)wdt_s)[i] = Wdt[i];
    for (int i = t; i < DI; i += 160) {
        bdt_s[i]  = bdt[i];
        dsum_s[i] = Dsg[i] + Dsg[DI + i] + Dsg[2 * DI + i] + Dsg[3 * DI + i];
    }
    __syncthreads();

    if (m == 0) {
        for (int i = t; i < 64 * DI; i += 160) {
            const int r = i / DI, c = i % DI;
            const size_t gi = ((size_t)b * LL + p0 + r) * DI + c;
            g_ysum[gi] = g_xca[gi] * dsum_s[c];
        }
    }

    float acc[4][4];
    #pragma unroll
    for (int i = 0; i < 4; i++)
        #pragma unroll
        for (int q = 0; q < 4; q++) acc[i][q] = 0.f;

    for (int kt = 0; kt < 6; kt++) {
        __syncthreads();
        for (int i = t; i < 64 * 32; i += 160) {
            const int r = i >> 5, c = i & 31;
            const int p = p0 + r;
            const int src = m ? (((p & 63) << 6) | (p >> 6)) : p;
            xs[r][c] = g_xca[((size_t)b * LL + src) * DI + kt * 32 + c];
        }
        for (int i = t; i < 32 * 40; i += 160) {
            const int k = i / 40, j = i % 40;
            ws[k][j] = (j < NPROJ) ? Wx[(kt * 32 + k) * NPROJ + j] : 0.f;
        }
        __syncthreads();

        #pragma unroll 8
        for (int kk = 0; kk < 32; kk++) {
            const float4 bv = *(const float4*)&ws[kk][tx * 4];
            const float a0 = xs[ty * 4 + 0][kk];
            const float a1 = xs[ty * 4 + 1][kk];
            const float a2 = xs[ty * 4 + 2][kk];
            const float a3 = xs[ty * 4 + 3][kk];
            acc[0][0] += a0 * bv.x; acc[0][1] += a0 * bv.y; acc[0][2] += a0 * bv.z; acc[0][3] += a0 * bv.w;
            acc[1][0] += a1 * bv.x; acc[1][1] += a1 * bv.y; acc[1][2] += a1 * bv.z; acc[1][3] += a1 * bv.w;
            acc[2][0] += a2 * bv.x; acc[2][1] += a2 * bv.y; acc[2][2] += a2 * bv.z; acc[2][3] += a2 * bv.w;
            acc[3][0] += a3 * bv.x; acc[3][1] += a3 * bv.y; acc[3][2] += a3 * bv.z; acc[3][3] += a3 * bv.w;
        }
    }
    #pragma unroll
    for (int i = 0; i < 4; i++)
        #pragma unroll
        for (int q = 0; q < 4; q++)
            xdbl[ty * 4 + i][tx * 4 + q] = acc[i][q];
    __syncthreads();

    {
        float2* bc2 = (float2*)(g_bc_raw + BCPAD);
        for (int i = t; i < 64 * 16; i += 160) {
            const int pi = i >> 4, n = i & 15;
            bc2[(((size_t)bm * LL + p0 + pi) * 8 + (n & 7)) * 2 + (n >> 3)] =
                make_float2(xdbl[pi][DR + n], xdbl[pi][DR + DS + n]);
        }
        // B pairs for scan1: float4 (Bj(2pp), Bj+8(2pp), Bj(2pp+1), Bj+8(2pp+1))
        float4* b2 = g_b2_raw + B2PAD;
        for (int i = t; i < 32 * 8; i += 160) {
            const int pp = i >> 3, jj = i & 7;
            b2[((size_t)bm * (LL / 2) + (p0 >> 1) + pp) * 8 + jj] =
                make_float4(xdbl[2 * pp][DR + jj],     xdbl[2 * pp][DR + 8 + jj],
                            xdbl[2 * pp + 1][DR + jj], xdbl[2 * pp + 1][DR + 8 + jj]);
        }
    }

    float2* dxw = g_dx_raw + DXPAD;
    for (int dt = 0; dt < 6; dt++) {
        __syncthreads();
        for (int i = t; i < 64 * 32; i += 160) {
            const int r = i >> 5, c = i & 31;
            const int p = p0 + r;
            const int src = m ? (((p & 63) << 6) | (p >> 6)) : p;
            xs[r][c] = g_xca[((size_t)b * LL + src) * DI + dt * 32 + c];
        }
        __syncthreads();
        for (int i = t; i < 32 * 64; i += 160) {
            const int dl = i >> 6, pi = i & 63;
            const int d = dt * 32 + dl;
            float v = bdt_s[d];
            #pragma unroll
            for (int r = 0; r < DR; r++) v += xdbl[pi][r] * wdt_s[r][d];
            const float sp = (v > 20.f) ? v : log1pf(__expf(v));
            dxw[((size_t)(bm * DI + d)) * LL + p0 + pi] = make_float2(sp, xs[pi][dl]);
        }
    }
}

// ---------------- scan macros ----------------
// scan1 (B-pair) loads: 2 dx float4 + 2 B-pair float4 per 4 positions
#define LOADB1(S, pd_, pq_)                                            \
    S##_dxa = (pd_)[0]; S##_dxb = (pd_)[1];                            \
    S##_b01 = (pq_)[0]; S##_b23 = (pq_)[8];

// scan2 (full bc) loads
#define LOADG(S, pd_, pb_)                                             \
    S##_dxa = (pd_)[0]; S##_dxb = (pd_)[1];                            \
    S##_c0 = (pb_)[0];  S##_c1 = (pb_)[8];                             \
    S##_c2 = (pb_)[16]; S##_c3 = (pb_)[24];

#define STEPQ(del, xv, Bl, Bh) {                                       \
    const float dA0 = ex2f((del) * A0);                                \
    const float dA1 = ex2f((del) * A1);                                \
    const float tv = (del) * (xv);                                     \
    h0 = fmaf(dA0, h0, tv * (Bl));                                     \
    h1 = fmaf(dA1, h1, tv * (Bh));                                     \
    sd += (del); }

#define STEPE(del, xv, bcv, yidx) {                                    \
    const float dA0 = ex2f((del) * A0);                                \
    const float dA1 = ex2f((del) * A1);                                \
    const float tv = (del) * (xv);                                     \
    h0 = fmaf(dA0, h0, tv * (bcv).x);                                  \
    h1 = fmaf(dA1, h1, tv * (bcv).z);                                  \
    float y = fmaf(h1, (bcv).w, h0 * (bcv).y);                         \
    y += __shfl_xor_sync(0xffffffffu, y, 1);                           \
    y += __shfl_xor_sync(0xffffffffu, y, 2);                           \
    if ((j & 3) == 0) atomicAdd(ysu + (yidx), y); }

#define TBASE(sp) ((size_t)(m ? (((sp & 63) << 6) | (sp >> 6)) : (sp)) * DI)

#define GBQ_F(S) {                                                     \
    STEPQ(S##_dxa.x, S##_dxa.y, S##_b01.x, S##_b01.y);                 \
    STEPQ(S##_dxa.z, S##_dxa.w, S##_b01.z, S##_b01.w);                 \
    STEPQ(S##_dxb.x, S##_dxb.y, S##_b23.x, S##_b23.y);                 \
    STEPQ(S##_dxb.z, S##_dxb.w, S##_b23.z, S##_b23.w); }

#define GBQ_R(S) {                                                     \
    STEPQ(S##_dxb.z, S##_dxb.w, S##_b23.z, S##_b23.w);                 \
    STEPQ(S##_dxb.x, S##_dxb.y, S##_b23.x, S##_b23.y);                 \
    STEPQ(S##_dxa.z, S##_dxa.w, S##_b01.z, S##_b01.w);                 \
    STEPQ(S##_dxa.x, S##_dxa.y, S##_b01.x, S##_b01.y); }

#define GBE_F(S, sp) { const size_t tb = TBASE(sp);                    \
    STEPE(S##_dxa.x, S##_dxa.y, S##_c0, tb);                           \
    STEPE(S##_dxa.z, S##_dxa.w, S##_c1, tb + stm);                     \
    STEPE(S##_dxb.x, S##_dxb.y, S##_c2, tb + 2 * stm);                 \
    STEPE(S##_dxb.z, S##_dxb.w, S##_c3, tb + 3 * stm); }

#define GBE_R(S, sp) { const size_t tb = TBASE(sp);                    \
    STEPE(S##_dxb.z, S##_dxb.w, S##_c3, tb + 3 * stm);                 \
    STEPE(S##_dxb.x, S##_dxb.y, S##_c2, tb + 2 * stm);                 \
    STEPE(S##_dxa.z, S##_dxa.w, S##_c1, tb + stm);                     \
    STEPE(S##_dxa.x, S##_dxa.y, S##_c0, tb); }

#define WALK1_F(lo, hi) {                                              \
    float4 s0_dxa, s0_dxb, s0_b01, s0_b23;                             \
    float4 s1_dxa, s1_dxb, s1_b01, s1_b23;                             \
    const float4* pd = (const float4*)(dxr + (lo));                    \
    const float4* pq = bqr + (size_t)((lo) >> 1) * 8;                  \
    LOADB1(s0, pd, pq);                                                \
    LOADB1(s1, pd + 2, pq + 16);                                       \
    const float4* pdn = pd + 4;                                        \
    const float4* pqn = pq + 32;                                       \
    for (int it = ((hi) - (lo)) >> 3; it > 0; it--) {                  \
        GBQ_F(s0);                                                     \
        LOADB1(s0, pdn, pqn);                                          \
        GBQ_F(s1);                                                     \
        LOADB1(s1, pdn + 2, pqn + 16);                                 \
        pdn += 4; pqn += 32;                                           \
    } }

#define WALK1_R(lo, hi) {                                              \
    float4 s0_dxa, s0_dxb, s0_b01, s0_b23;                             \
    float4 s1_dxa, s1_dxb, s1_b01, s1_b23;                             \
    const float4* pd = (const float4*)(dxr + (hi)) - 2;                \
    const float4* pq = bqr + (size_t)((hi) >> 1) * 8 - 16;             \
    LOADB1(s0, pd, pq);                                                \
    LOADB1(s1, pd - 2, pq - 16);                                       \
    const float4* pdn = pd - 4;                                        \
    const float4* pqn = pq - 32;                                       \
    for (int it = ((hi) - (lo)) >> 3; it > 0; it--) {                  \
        GBQ_R(s0);                                                     \
        LOADB1(s0, pdn, pqn);                                          \
        GBQ_R(s1);                                                     \
        LOADB1(s1, pdn - 2, pqn - 16);                                 \
        pdn -= 4; pqn -= 32;                                           \
    } }

#define WALK_F(lo, hi, GB) {                                           \
    float4 s0_dxa, s0_dxb, s0_c0, s0_c1, s0_c2, s0_c3;                 \
    float4 s1_dxa, s1_dxb, s1_c0, s1_c1, s1_c2, s1_c3;                 \
    const float4* pd = (const float4*)(dxr + (lo));                    \
    const float4* pb = bcr + (size_t)(lo) * 8;                         \
    LOADG(s0, pd, pb);                                                 \
    LOADG(s1, pd + 2, pb + 32);                                        \
    const float4* pdn = pd + 4;                                        \
    const float4* pbn = pb + 64;                                       \
    int sp = (lo);                                                     \
    for (int it = ((hi) - (lo)) >> 3; it > 0; it--) {                  \
        GB(s0, sp);                                                    \
        LOADG(s0, pdn, pbn);                                           \
        GB(s1, (sp + 4));                                              \
        LOADG(s1, pdn + 2, pbn + 32);                                  \
        pdn += 4; pbn += 64; sp += 8;                                  \
    } }

#define WALK_R(lo, hi, GB) {                                           \
    float4 s0_dxa, s0_dxb, s0_c0, s0_c1, s0_c2, s0_c3;                 \
    float4 s1_dxa, s1_dxb, s1_c0, s1_c1, s1_c2, s1_c3;                 \
    const float4* pd = (const float4*)(dxr + (hi) - 4);                \
    const float4* pb = bcr + (size_t)((hi) - 4) * 8;                   \
    LOADG(s0, pd, pb);                                                 \
    LOADG(s1, pd - 2, pb - 32);                                        \
    const float4* pdn = pd - 4;                                        \
    const float4* pbn = pb - 64;                                       \
    int sp = (hi) - 4;                                                 \
    for (int it = ((hi) - (lo)) >> 3; it > 0; it--) {                  \
        GB(s0, sp);                                                    \
        LOADG(s0, pdn, pbn);                                           \
        GB(s1, (sp - 4));                                              \
        LOADG(s1, pdn - 2, pbn - 32);                                  \
        pdn -= 4; pbn -= 64; sp -= 8;                                  \
    } }

// ---------------- kernel 4a: phase-1 chunk summaries (128 thr = 16 d) --------
__global__ __launch_bounds__(128) void k_scan1(const float* __restrict__ A_logs) {
    const int k  = blockIdx.y >> 4;
    const int ch = blockIdx.y & 15;
    if (ch == CHN - 1) return;                 // last chunk summary feeds nothing
    const int b  = blockIdx.z;
    const int lane = threadIdx.x & 31;
    const int d  = blockIdx.x * 16 + (threadIdx.x >> 5) * 4 + (lane >> 3);
    const int j  = lane & 7;
    const int m = k >> 1, rev = k & 1;
    const int bm = b * 2 + m;
    const float L2E = 1.4426950408889634f;

    const float A0 = -__expf(__ldg(&A_logs[(k * DI + d) * DS + j]))     * L2E;
    const float A1 = -__expf(__ldg(&A_logs[(k * DI + d) * DS + j + 8])) * L2E;

    const float2* dxr = g_dx_raw + DXPAD + (size_t)(bm * DI + d) * LL;
    const float4* bqr = g_b2_raw + B2PAD + (size_t)bm * (LL / 2) * 8 + j;

    float h0 = 0.f, h1 = 0.f, sd = 0.f;

    if (!rev) { WALK1_F(ch * CH2, (ch + 1) * CH2); }
    else      { WALK1_R(LL - (ch + 1) * CH2, LL - ch * CH2); }

    const int base = (((b * 4 + k) * CHN + ch) * DI + d) * 16;
    g_h[base + j]     = h0;
    g_h[base + j + 8] = h1;
    if (j == 0) g_sd[((b * 4 + k) * CHN + ch) * DI + d] = sd;
}

// ---------------- kernel 4c: phase-3 emit, prefix fused (128 thr = 16 d) -----
__global__ __launch_bounds__(128) void k_scan2(const float* __restrict__ A_logs) {
    const int k  = blockIdx.y >> 4;
    const int ch = blockIdx.y & 15;            // chunk in scan order
    const int b  = blockIdx.z;
    const int lane = threadIdx.x & 31;
    const int d  = blockIdx.x * 16 + (threadIdx.x >> 5) * 4 + (lane >> 3);
    const int j  = lane & 7;
    const int m = k >> 1, rev = k & 1;
    const int bm = b * 2 + m;
    const float L2E = 1.4426950408889634f;

    const float A0 = -__expf(__ldg(&A_logs[(k * DI + d) * DS + j]))     * L2E;
    const float A1 = -__expf(__ldg(&A_logs[(k * DI + d) * DS + j + 8])) * L2E;

    const float2* dxr = g_dx_raw + DXPAD + (size_t)(bm * DI + d) * LL;
    const float4* bcr = g_bc_raw + BCPAD + (size_t)bm * LL * 8 + j;
    float* ysu = g_ysum + (size_t)b * LL * DI + d;
    const size_t stm = (size_t)(m ? 64 : 1) * DI;

    // incoming state: combine chunk summaries 0..ch-1 (scan order)
    float h0 = 0.f, h1 = 0.f;
    for (int c = 0; c < ch; c++) {
        const int bc_ = ((b * 4 + k) * CHN + c) * DI + d;
        const float sdv = g_sd[bc_];
        h0 = fmaf(ex2f(A0 * sdv), h0, g_h[bc_ * 16 + j]);
        h1 = fmaf(ex2f(A1 * sdv), h1, g_h[bc_ * 16 + j + 8]);
    }

    if (!rev) { WALK_F(ch * CH2, (ch + 1) * CH2, GBE_F); }
    else      { WALK_R(LL - (ch + 1) * CH2, LL - ch * CH2, GBE_R); }
}

// ---------------- kernel 5: out = (ysum * siluz) @ W_out ----------------
__global__ void k_out(const float* __restrict__ Wout, float* __restrict__ out) {
    __shared__ __align__(16) float ins[64][96];
    __shared__ __align__(16) float ws[96][32];
    const int t = threadIdx.x;                    // 128
    const int row0 = blockIdx.x * 64;
    const int col0 = blockIdx.y * 32;
    const int tx = t & 7, ty = t >> 3;

    float acc[4][4];
    #pragma unroll
    for (int i = 0; i < 4; i++)
        #pragma unroll
        for (int jj = 0; jj < 4; jj++) acc[i][jj] = 0.f;

    for (int kc = 0; kc < 2; kc++) {
        __syncthreads();
        #pragma unroll
        for (int i = 0; i < 12; i++) {
            const int idx = t + i * 128;
            const int r = idx / 24, k4 = idx % 24;
            const size_t gi = (size_t)(row0 + r) * DI + kc * 96 + k4 * 4;
            const float4 a = *(const float4*)&g_ysum[gi];
            const float4 z = *(const float4*)&g_siluz[gi];
            *(float4*)&ins[r][k4 * 4] = make_float4(a.x * z.x, a.y * z.y, a.z * z.z, a.w * z.w);
        }
        #pragma unroll
        for (int i = 0; i < 6; i++) {
            const int idx = t + i * 128;
            const int kk = idx / 8, c4 = idx % 8;
            *(float4*)&ws[kk][c4 * 4] = *(const float4*)&Wout[(kc * 96 + kk) * DM + col0 + c4 * 4];
        }
        __syncthreads();

        #pragma unroll 8
        for (int kk = 0; kk < 96; kk++) {
            const float4 bv = *(const float4*)&ws[kk][tx * 4];
            const float a0 = ins[ty * 4 + 0][kk];
            const float a1 = ins[ty * 4 + 1][kk];
            const float a2 = ins[ty * 4 + 2][kk];
            const float a3 = ins[ty * 4 + 3][kk];
            acc[0][0] += a0 * bv.x; acc[0][1] += a0 * bv.y; acc[0][2] += a0 * bv.z; acc[0][3] += a0 * bv.w;
            acc[1][0] += a1 * bv.x; acc[1][1] += a1 * bv.y; acc[1][2] += a1 * bv.z; acc[1][3] += a1 * bv.w;
            acc[2][0] += a2 * bv.x; acc[2][1] += a2 * bv.y; acc[2][2] += a2 * bv.z; acc[2][3] += a2 * bv.w;
            acc[3][0] += a3 * bv.x; acc[3][1] += a3 * bv.y; acc[3][2] += a3 * bv.z; acc[3][3] += a3 * bv.w;
        }
    }

    #pragma unroll
    for (int i = 0; i < 4; i++) {
        const int row = row0 + ty * 4 + i;
        *(float4*)&out[(size_t)row * DM + col0 + tx * 4] =
            make_float4(acc[i][0], acc[i][1], acc[i][2], acc[i][3]);
    }
}

// ---------------- launch ----------------
extern "C" void kernel_launch(void* const* d_in, const int* in_sizes, int n_in,
                              void* d_out, int out_size) {
    const float* x     = (const float*)d_in[0];
    const float* Win   = (const float*)d_in[1];
    const float* cw    = (const float*)d_in[2];
    const float* cb    = (const float*)d_in[3];
    const float* Wx    = (const float*)d_in[4];
    const float* Wdt   = (const float*)d_in[5];
    const float* bdt   = (const float*)d_in[6];
    const float* Alogs = (const float*)d_in[7];
    const float* Ds    = (const float*)d_in[8];
    const float* Wout  = (const float*)d_in[9];
    float* out = (float*)d_out;

    dim3 gg(BB * LL / 64, 6);
    k_in_gemm<<<gg, 256>>>(x, Win);
    k_conv<<<(BB * LL * (DI / 4) + 255) / 256, 256>>>(cw, cb);
    dim3 gp(LL / 64, 2, BB);
    k_proj<<<gp, 160>>>(Wx, Wdt, bdt, Ds);
    dim3 gs(DI / 16, 4 * CHN, BB);       // y = dir*16 + chunk
    k_scan1<<<gs, 128>>>(Alogs);
    k_scan2<<<gs, 128>>>(Alogs);
    dim3 go(BB * LL / 64, 3);
    k_out<<<go, 128>>>(Wout, out);
}